// round 17
// baseline (speedup 1.0000x reference)
#include <cuda_runtime.h>
#include <cstdint>

// TtLlamaRotary: out[n,s,:] = x[n,s,:] @ R[s,:,:]
//   xq [8,128,128], xk [1,128,128], rot [128,128,128], out concat (9,128,128)
//
// One CTA per seq position s (grid 128, block 512 = 16 h-groups x 32 threads).
// Thread owns 4 output columns; x staged once per CTA. Staging LDGs issue
// FIRST (they gate the block barrier; L1tex completes in issue order),
// R prefetch second — loaded directly as ulonglong2 so the f32x2 operands
// need NO packing movs. Inner loop: one LDS.128 feeds 2 h-steps, packed
// fma.rn.f32x2; partials stored as raw u64 pairs (no unpack movs).
// Balanced 512-thread two-accumulator f32x2 reduction.

#define SEQ_LEN 128
#define HEAD_DIM 128
#define NQ 8
#define NROWS 9
#define TPG 32
#define NGROUPS 16
#define HCHUNK 8
#define NTHREADS 512
#define NCHUNK2 (NROWS * (HEAD_DIM / 2))     // 576 float2 chunks

// dynamic smem layout (bytes)
#define SM_X     0                           // 9*128*8 = 9216 (dup float2)
#define SM_PART  9216                        // 16*9*128*4 = 73728
#define SM_TOTAL (SM_PART + 73728)           // 82944

__global__ __launch_bounds__(NTHREADS, 1)
void rotary_kernel(const float* __restrict__ xq,
                   const float* __restrict__ xk,
                   const float* __restrict__ rot,
                   float* __restrict__ out) {
    extern __shared__ char smem[];
    float2* xs2  = (float2*)(smem + SM_X);      // [9][128] duplicated
    float*  part = (float*)(smem + SM_PART);    // [16][9][128]

    const int s   = blockIdx.x;
    const int tid = threadIdx.x;
    const int g   = tid / TPG;        // h-group 0..15
    const int t   = tid % TPG;        // 4-col slot 0..31

    // ---- Stage x FIRST: 576 float2 chunks over 512 threads ----
    // These loads gate the barrier; issue them ahead of the R prefetch so
    // they drain from the L1tex queue first.
    #pragma unroll
    for (int idx = tid; idx < NCHUNK2; idx += NTHREADS) {
        const int n = idx >> 6;
        const int c = idx & 63;
        const float2 v = (n < NQ)
            ? *(const float2*)(xq + ((size_t)(n * SEQ_LEN + s) * HEAD_DIM) + c * 2)
            : *(const float2*)(xk + ((size_t)s * HEAD_DIM) + c * 2);
        // duplicated pair -> one STS.128
        *(float4*)&xs2[n * HEAD_DIM + c * 2] = make_float4(v.x, v.x, v.y, v.y);
    }

    // ---- Prefetch R slice as raw u64 pairs (no f32x2 packing needed) ----
    const ulonglong2* __restrict__ R4 =
        (const ulonglong2*)rot + (size_t)s * (HEAD_DIM * HEAD_DIM / 4) + t;
    ulonglong2 rv[HCHUNK];   // rv[h].x = {R[h][4t],R[h][4t+1]}, .y = next pair
    #pragma unroll
    for (int h = 0; h < HCHUNK; h++)
        rv[h] = R4[(size_t)(g * HCHUNK + h) * (HEAD_DIM / 4)];

    __syncthreads();

    // ---- Accumulate: 4 h-pairs x 9 rows; LDS.128 feeds 2 h-steps ----
    unsigned long long acc01[NROWS], acc23[NROWS];
    #pragma unroll
    for (int n = 0; n < NROWS; n++) { acc01[n] = 0ull; acc23[n] = 0ull; }

    #pragma unroll
    for (int hp = 0; hp < HCHUNK / 2; hp++) {
        const int hh = g * HCHUNK + hp * 2;
        const unsigned long long rA01 = rv[hp*2].x,   rA23 = rv[hp*2].y;
        const unsigned long long rB01 = rv[hp*2+1].x, rB23 = rv[hp*2+1].y;
        #pragma unroll
        for (int n = 0; n < NROWS; n++) {
            // one LDS.128: {x_h, x_h, x_h1, x_h1}
            const ulonglong2 xp = *(const ulonglong2*)&xs2[n * HEAD_DIM + hh];
            asm("fma.rn.f32x2 %0, %1, %2, %0;" : "+l"(acc01[n]) : "l"(xp.x), "l"(rA01));
            asm("fma.rn.f32x2 %0, %1, %2, %0;" : "+l"(acc23[n]) : "l"(xp.x), "l"(rA23));
            asm("fma.rn.f32x2 %0, %1, %2, %0;" : "+l"(acc01[n]) : "l"(xp.y), "l"(rB01));
            asm("fma.rn.f32x2 %0, %1, %2, %0;" : "+l"(acc23[n]) : "l"(xp.y), "l"(rB23));
        }
    }

    // ---- Write partials as raw u64 pairs (STS.128, no unpack movs) ----
    #pragma unroll
    for (int n = 0; n < NROWS; n++) {
        ulonglong2 pw;
        pw.x = acc01[n];
        pw.y = acc23[n];
        *(ulonglong2*)&part[(g * NROWS + n) * HEAD_DIM + t * 4] = pw;
    }
    __syncthreads();

    // ---- Reduce 16 partials: 576 float2 outputs over 512 threads ----
    // Two accumulators halve the serial add chain.
    #pragma unroll
    for (int idx = tid; idx < NCHUNK2; idx += NTHREADS) {
        const int n = idx >> 6;
        const int c = idx & 63;
        unsigned long long va = 0ull, vb = 0ull;
        #pragma unroll
        for (int gg = 0; gg < NGROUPS; gg += 2) {
            const unsigned long long pa =
                *(const unsigned long long*)&part[(gg * NROWS + n) * HEAD_DIM + c * 2];
            const unsigned long long pb =
                *(const unsigned long long*)&part[((gg + 1) * NROWS + n) * HEAD_DIM + c * 2];
            asm("add.rn.f32x2 %0, %0, %1;" : "+l"(va) : "l"(pa));
            asm("add.rn.f32x2 %0, %0, %1;" : "+l"(vb) : "l"(pb));
        }
        asm("add.rn.f32x2 %0, %0, %1;" : "+l"(va) : "l"(vb));
        // n==8 lands exactly at the xk output block (uniform indexing).
        const size_t o = (size_t)(n * SEQ_LEN + s) * HEAD_DIM + c * 2;
        *(unsigned long long*)(out + o) = va;
    }
}

extern "C" void kernel_launch(void* const* d_in, const int* in_sizes, int n_in,
                              void* d_out, int out_size) {
    const float* xq  = (const float*)d_in[0];
    const float* xk  = (const float*)d_in[1];
    const float* rot = (const float*)d_in[2];
    float* out = (float*)d_out;

    cudaFuncSetAttribute(rotary_kernel,
                         cudaFuncAttributeMaxDynamicSharedMemorySize, SM_TOTAL);
    rotary_kernel<<<SEQ_LEN, NTHREADS, SM_TOTAL>>>(xq, xk, rot, out);
}